// round 14
// baseline (speedup 1.0000x reference)
#include <cuda_runtime.h>

#define NB 4
#define NN 32768
#define NE 262144
#define CHV 16
#define CHE 16
#define HID 64
#define CHM 48   // 2*CHV + CHE

typedef unsigned long long u64;

// ---------------- scratch (static device memory; no allocation) ----------------
__device__ float g_agg_a[NB * NN * CHV];   // 8 MB
__device__ float g_agg_b[NB * NN * CHV];   // 8 MB
__device__ int   g_cnt_a[NN];
__device__ int   g_cnt_b[NN];
__device__ float g_inv_a[NN];
__device__ float g_inv_b[NN];

// ---------------- constant-memory weights --------------------------------------
// Port balance (R9/R13 evidence): const port floor=8/LDC => keep const issue
// cycles under the fma pipe (6144/item). W1 full (384 LDC) + W2 rows 32..63
// (192 LDC) = 4608 < 6144. W2 rows 0..31 stay on SMEM/L1tex.
__constant__ __align__(16) float cEW1[CHM * HID];        // edge W1 (48,64) 12 KB
__constant__ __align__(16) float cEW2H[(HID/2) * CHM];   // edge W2 rows 32..63, 6 KB
__constant__ __align__(16) float cEb1[HID];
__constant__ __align__(16) float cEb2[CHM];
__constant__ __align__(16) float cNW1[CHM * HID];        // node W1 (48,64) 12 KB
__constant__ __align__(16) float cNb1[HID];
__constant__ __align__(16) float cNb2[CHV];

// ---------------- helpers ----------------
__device__ __forceinline__ u64 pack2(float lo, float hi) {
    u64 r;
    asm("mov.b64 %0, {%1, %2};" : "=l"(r) : "f"(lo), "f"(hi));
    return r;
}
__device__ __forceinline__ void unpack2(u64 v, float& lo, float& hi) {
    asm("mov.b64 {%0, %1}, %2;" : "=f"(lo), "=f"(hi) : "l"(v));
}
// packed dual-fp32 fma (sm_100+): d = a*b + c on both lanes
__device__ __forceinline__ u64 fma2(u64 a, u64 b, u64 c) {
    u64 d;
    asm("fma.rn.f32x2 %0, %1, %2, %3;" : "=l"(d) : "l"(a), "l"(b), "l"(c));
    return d;
}
// accurate-enough fast tanh: 1 - 2/(e^2x + 1); MUFU.EX2 + MUFU.RCP, ~1e-6 rel err
__device__ __forceinline__ float fast_tanh(float x) {
    float e = __expf(2.0f * x);
    return 1.0f - __fdividef(2.0f, e + 1.0f);
}
// Vectorized global reduction (sm_90+)
__device__ __forceinline__ void red_add_v4(float* addr, float x, float y, float z, float w) {
    asm volatile("red.global.add.v4.f32 [%0], {%1, %2, %3, %4};"
                 :: "l"(addr), "f"(x), "f"(y), "f"(z), "f"(w) : "memory");
}

// Consume one input scalar into all 64 hidden accumulators (W1 in __constant__).
template<int I>
__device__ __forceinline__ void consume1(const float* W, u64* acc, float x) {
    u64 hh = pack2(x, x);
    const ulonglong2* w = (const ulonglong2*)(W + I * HID);
    #pragma unroll
    for (int q = 0; q < HID / 4; q++) {
        ulonglong2 wv = w[q];
        acc[2 * q + 0] = fma2(hh, wv.x, acc[2 * q + 0]);
        acc[2 * q + 1] = fma2(hh, wv.y, acc[2 * q + 1]);
    }
}
template<int I0>
__device__ __forceinline__ void consume4(const float* W, u64* acc, float4 v) {
    consume1<I0 + 0>(W, acc, v.x);
    consume1<I0 + 1>(W, acc, v.y);
    consume1<I0 + 2>(W, acc, v.z);
    consume1<I0 + 3>(W, acc, v.w);
}

// One layer-2 row pair: m[] += tanh-pair broadcast * W2row (CHM wide).
__device__ __forceinline__ void l2_rowpair(const float* Wrow0, const float* Wrow1,
                                           u64 acc_pair, u64* m, int width) {
    float lo, hi;
    unpack2(acc_pair, lo, hi);
    u64 t0 = pack2(fast_tanh(lo), fast_tanh(lo));
    u64 t1 = pack2(fast_tanh(hi), fast_tanh(hi));
    const ulonglong2* w0 = (const ulonglong2*)Wrow0;
    const ulonglong2* w1 = (const ulonglong2*)Wrow1;
    #pragma unroll
    for (int q = 0; q < 12; q++) {   // width/4 == 12 for CHM
        if (4 * q >= width) break;
        ulonglong2 wv0 = w0[q];
        m[2 * q + 0] = fma2(t0, wv0.x, m[2 * q + 0]);
        m[2 * q + 1] = fma2(t0, wv0.y, m[2 * q + 1]);
        ulonglong2 wv1 = w1[q];
        m[2 * q + 0] = fma2(t1, wv1.x, m[2 * q + 0]);
        m[2 * q + 1] = fma2(t1, wv1.y, m[2 * q + 1]);
    }
}

// ---------------- setup kernels ----------------
__global__ void zero_kernel() {
    int i = blockIdx.x * blockDim.x + threadIdx.x;
    const int n4 = NB * NN * CHV / 4;
    if (i < n4) {
        ((float4*)g_agg_a)[i] = make_float4(0.f, 0.f, 0.f, 0.f);
        ((float4*)g_agg_b)[i] = make_float4(0.f, 0.f, 0.f, 0.f);
    }
    if (i < NN) { g_cnt_a[i] = 0; g_cnt_b[i] = 0; }
}

__global__ void count_kernel(const int* __restrict__ ca, const int* __restrict__ cb) {
    int e = blockIdx.x * blockDim.x + threadIdx.x;
    if (e < NE) {
        atomicAdd(&g_cnt_a[ca[e]], 1);
        atomicAdd(&g_cnt_b[cb[e]], 1);
    }
}

__global__ void inv_kernel() {
    int n = blockIdx.x * blockDim.x + threadIdx.x;
    if (n < NN) {
        g_inv_a[n] = 1.0f / fmaxf((float)g_cnt_a[n], 1.0f);
        g_inv_b[n] = 1.0f / fmaxf((float)g_cnt_b[n], 1.0f);
    }
}

// ---------------- edge message kernel ----------------
// One thread per (batch, edge). Streaming inputs; W1 const; W2 split:
// rows 0..31 from SMEM (L1tex), rows 32..63 from constant port.
__global__ __launch_bounds__(128, 4) void edge_kernel(
    const float* __restrict__ nv, const float* __restrict__ ev,
    const int* __restrict__ ca, const int* __restrict__ cb,
    const float* __restrict__ W2,
    float* __restrict__ out_edge)
{
    __shared__ __align__(16) float sW2L[(HID/2) * CHM];   // W2 rows 0..31, 6 KB
    for (int i = threadIdx.x; i < (HID/2) * CHM; i += 128) sW2L[i] = W2[i];
    __syncthreads();

    int t = blockIdx.x * 128 + threadIdx.x;   // exactly NB*NE threads
    int b = t >> 18;                          // t / NE
    int e = t & (NE - 1);

    int na = ca[e];
    int nb = cb[e];

    const float4* pa = (const float4*)(nv + ((b << 15) + na) * CHV);
    const float4* pb = (const float4*)(nv + ((b << 15) + nb) * CHV);
    const float4* pe = (const float4*)(ev + (size_t)t * CHE);

    // Layer 1: 32 packed accumulators (64 hidden), inputs consumed on the fly
    u64 acc[HID / 2];
    {
        const u64* b1p = (const u64*)cEb1;
        #pragma unroll
        for (int p = 0; p < HID / 2; p++) acc[p] = b1p[p];
    }
    consume4< 0>(cEW1, acc, pa[0]);
    consume4< 4>(cEW1, acc, pa[1]);
    consume4< 8>(cEW1, acc, pa[2]);
    consume4<12>(cEW1, acc, pa[3]);
    consume4<16>(cEW1, acc, pb[0]);
    consume4<20>(cEW1, acc, pb[1]);
    consume4<24>(cEW1, acc, pb[2]);
    consume4<28>(cEW1, acc, pb[3]);
    consume4<32>(cEW1, acc, pe[0]);
    consume4<36>(cEW1, acc, pe[1]);
    consume4<40>(cEW1, acc, pe[2]);
    consume4<44>(cEW1, acc, pe[3]);

    // Layer 2 (tanh fused): interleave SMEM rows (j=2p,2p+1) with const rows
    // (j=32+2p,32+2p+1) each iteration — both load ports stay busy.
    u64 m[CHM / 2];
    {
        const u64* b2p = (const u64*)cEb2;
        #pragma unroll
        for (int p = 0; p < CHM / 2; p++) m[p] = b2p[p];
    }
    #pragma unroll
    for (int p = 0; p < HID / 4; p++) {      // p = 0..15
        l2_rowpair(sW2L  + (2 * p)     * CHM, sW2L  + (2 * p + 1) * CHM,
                   acc[p], m, CHM);
        l2_rowpair(cEW2H + (2 * p)     * CHM, cEW2H + (2 * p + 1) * CHM,
                   acc[16 + p], m, CHM);
    }

    float mv[CHM];
    #pragma unroll
    for (int p = 0; p < CHM / 2; p++) unpack2(m[p], mv[2 * p], mv[2 * p + 1]);

    // Scatter m_a, m_b with 16B global reductions
    float* aga = g_agg_a + ((b << 15) + na) * CHV;
    red_add_v4(aga + 0,  mv[0],  mv[1],  mv[2],  mv[3]);
    red_add_v4(aga + 4,  mv[4],  mv[5],  mv[6],  mv[7]);
    red_add_v4(aga + 8,  mv[8],  mv[9],  mv[10], mv[11]);
    red_add_v4(aga + 12, mv[12], mv[13], mv[14], mv[15]);

    float* agb = g_agg_b + ((b << 15) + nb) * CHV;
    red_add_v4(agb + 0,  mv[16], mv[17], mv[18], mv[19]);
    red_add_v4(agb + 4,  mv[20], mv[21], mv[22], mv[23]);
    red_add_v4(agb + 8,  mv[24], mv[25], mv[26], mv[27]);
    red_add_v4(agb + 12, mv[28], mv[29], mv[30], mv[31]);

    // new_edge_vals = edge_vals + m_ab (re-read ev; L1 hit)
    {
        float4* oe = (float4*)(out_edge + (size_t)t * CHE);
        #pragma unroll
        for (int q = 0; q < 4; q++) {
            float4 evv = pe[q];
            oe[q] = make_float4(evv.x + mv[32 + 4 * q],
                                evv.y + mv[33 + 4 * q],
                                evv.z + mv[34 + 4 * q],
                                evv.w + mv[35 + 4 * q]);
        }
    }
}

// ---------------- node update kernel ----------------
// NW1 const, NW2 SMEM (small kernel; keep simple). Switch-free streaming.
__global__ __launch_bounds__(128, 4) void node_kernel(
    const float* __restrict__ nv,
    const float* __restrict__ W2,
    float* __restrict__ out_node)
{
    __shared__ __align__(16) float sW2[HID * CHV];   // (64,16) 4 KB
    for (int i = threadIdx.x; i < HID * CHV; i += 128) sW2[i] = W2[i];
    __syncthreads();

    int t = blockIdx.x * 128 + threadIdx.x;   // exactly NB*NN threads
    int n = t & (NN - 1);

    float inva = g_inv_a[n];
    float invb = g_inv_b[n];

    const float4* pa = (const float4*)(g_agg_a + t * CHV);
    const float4* pb = (const float4*)(g_agg_b + t * CHV);
    const float4* pn = (const float4*)(nv + t * CHV);

    u64 acc[HID / 2];
    {
        const u64* b1p = (const u64*)cNb1;
        #pragma unroll
        for (int p = 0; p < HID / 2; p++) acc[p] = b1p[p];
    }
    {
        float4 v;
        v = pa[0]; v.x *= inva; v.y *= inva; v.z *= inva; v.w *= inva; consume4< 0>(cNW1, acc, v);
        v = pa[1]; v.x *= inva; v.y *= inva; v.z *= inva; v.w *= inva; consume4< 4>(cNW1, acc, v);
        v = pa[2]; v.x *= inva; v.y *= inva; v.z *= inva; v.w *= inva; consume4< 8>(cNW1, acc, v);
        v = pa[3]; v.x *= inva; v.y *= inva; v.z *= inva; v.w *= inva; consume4<12>(cNW1, acc, v);
        v = pb[0]; v.x *= invb; v.y *= invb; v.z *= invb; v.w *= invb; consume4<16>(cNW1, acc, v);
        v = pb[1]; v.x *= invb; v.y *= invb; v.z *= invb; v.w *= invb; consume4<20>(cNW1, acc, v);
        v = pb[2]; v.x *= invb; v.y *= invb; v.z *= invb; v.w *= invb; consume4<24>(cNW1, acc, v);
        v = pb[3]; v.x *= invb; v.y *= invb; v.z *= invb; v.w *= invb; consume4<28>(cNW1, acc, v);
    }
    consume4<32>(cNW1, acc, pn[0]);
    consume4<36>(cNW1, acc, pn[1]);
    consume4<40>(cNW1, acc, pn[2]);
    consume4<44>(cNW1, acc, pn[3]);

    u64 m[CHV / 2];
    {
        const u64* b2p = (const u64*)cNb2;
        #pragma unroll
        for (int p = 0; p < CHV / 2; p++) m[p] = b2p[p];
    }
    #pragma unroll
    for (int p = 0; p < HID / 2; p++) {
        float lo, hi;
        unpack2(acc[p], lo, hi);
        u64 t0 = pack2(fast_tanh(lo), fast_tanh(lo));
        u64 t1 = pack2(fast_tanh(hi), fast_tanh(hi));
        const ulonglong2* w0 = (const ulonglong2*)(sW2 + (2 * p)     * CHV);
        const ulonglong2* w1 = (const ulonglong2*)(sW2 + (2 * p + 1) * CHV);
        #pragma unroll
        for (int q = 0; q < CHV / 4; q++) {
            ulonglong2 wv0 = w0[q];
            m[2 * q + 0] = fma2(t0, wv0.x, m[2 * q + 0]);
            m[2 * q + 1] = fma2(t0, wv0.y, m[2 * q + 1]);
            ulonglong2 wv1 = w1[q];
            m[2 * q + 0] = fma2(t1, wv1.x, m[2 * q + 0]);
            m[2 * q + 1] = fma2(t1, wv1.y, m[2 * q + 1]);
        }
    }

    float upd[CHV];
    #pragma unroll
    for (int p = 0; p < CHV / 2; p++) unpack2(m[p], upd[2 * p], upd[2 * p + 1]);

    {
        float4* on = (float4*)(out_node + t * CHV);
        #pragma unroll
        for (int q = 0; q < 4; q++) {
            float4 v = pn[q];
            on[q] = make_float4(v.x + upd[4 * q + 0], v.y + upd[4 * q + 1],
                                v.z + upd[4 * q + 2], v.w + upd[4 * q + 3]);
        }
    }
}

// ---------------- launch ----------------
extern "C" void kernel_launch(void* const* d_in, const int* in_sizes, int n_in,
                              void* d_out, int out_size) {
    const float* nv  = (const float*)d_in[0];
    const float* ev  = (const float*)d_in[1];
    const int*   ca  = (const int*)  d_in[2];
    const int*   cb  = (const int*)  d_in[3];
    const float* Wm1 = (const float*)d_in[4];
    const float* bm1 = (const float*)d_in[5];
    const float* Wm2 = (const float*)d_in[6];
    const float* bm2 = (const float*)d_in[7];
    const float* Wu1 = (const float*)d_in[8];
    const float* bu1 = (const float*)d_in[9];
    const float* Wu2 = (const float*)d_in[10];
    const float* bu2 = (const float*)d_in[11];

    float* out      = (float*)d_out;
    float* out_node = out;                       // (B, NN, CHV) first
    float* out_edge = out + NB * NN * CHV;       // (B, NE, CHE) second

    // Stage weights into constant memory (D2D, capturable)
    cudaMemcpyToSymbolAsync(cEW1,  Wm1, CHM * HID * sizeof(float), 0, cudaMemcpyDeviceToDevice, 0);
    cudaMemcpyToSymbolAsync(cEW2H, Wm2 + (HID/2) * CHM, (HID/2) * CHM * sizeof(float), 0, cudaMemcpyDeviceToDevice, 0);
    cudaMemcpyToSymbolAsync(cEb1,  bm1, HID * sizeof(float),       0, cudaMemcpyDeviceToDevice, 0);
    cudaMemcpyToSymbolAsync(cEb2,  bm2, CHM * sizeof(float),       0, cudaMemcpyDeviceToDevice, 0);
    cudaMemcpyToSymbolAsync(cNW1,  Wu1, CHM * HID * sizeof(float), 0, cudaMemcpyDeviceToDevice, 0);
    cudaMemcpyToSymbolAsync(cNb1,  bu1, HID * sizeof(float),       0, cudaMemcpyDeviceToDevice, 0);
    cudaMemcpyToSymbolAsync(cNb2,  bu2, CHV * sizeof(float),       0, cudaMemcpyDeviceToDevice, 0);

    zero_kernel <<< (NB * NN * CHV / 4 + 255) / 256, 256 >>> ();
    count_kernel<<< NE / 256, 256 >>> (ca, cb);
    inv_kernel  <<< NN / 256, 256 >>> ();
    edge_kernel <<< NB * NE / 128, 128 >>> (nv, ev, ca, cb, Wm2, out_edge);
    node_kernel <<< NB * NN / 128, 128 >>> (nv, Wu2, out_node);
}

// round 15
// speedup vs baseline: 1.6630x; 1.6630x over previous
#include <cuda_runtime.h>

#define NB 4
#define NN 32768
#define NE 262144
#define CHV 16
#define CHE 16
#define HID 64
#define CHM 48   // 2*CHV + CHE

typedef unsigned long long u64;

// ---------------- scratch (static device memory; no allocation) ----------------
__device__ float g_agg_a[NB * NN * CHV];   // 8 MB
__device__ float g_agg_b[NB * NN * CHV];   // 8 MB
__device__ int   g_cnt_a[NN];
__device__ int   g_cnt_b[NN];
__device__ float g_inv_a[NN];
__device__ float g_inv_b[NN];

// ---------------- constant-memory: layer-1 weights + biases (R6/R13 split) -----
// Accessed ONLY through the symbols directly (never via pointer params — R14
// showed pointer-passing demotes LDC to generic LDG).
__constant__ __align__(16) float cEW1[CHM * HID];   // edge W1 (48,64) 12 KB
__constant__ __align__(16) float cEb1[HID];
__constant__ __align__(16) float cEb2[CHM];
__constant__ __align__(16) float cNW1[CHM * HID];   // node W1 (48,64) 12 KB
__constant__ __align__(16) float cNb1[HID];
__constant__ __align__(16) float cNb2[CHV];

// ---------------- helpers ----------------
__device__ __forceinline__ u64 pack2(float lo, float hi) {
    u64 r;
    asm("mov.b64 %0, {%1, %2};" : "=l"(r) : "f"(lo), "f"(hi));
    return r;
}
__device__ __forceinline__ void unpack2(u64 v, float& lo, float& hi) {
    asm("mov.b64 {%0, %1}, %2;" : "=f"(lo), "=f"(hi) : "l"(v));
}
// packed dual-fp32 fma (sm_100+): d = a*b + c on both lanes
__device__ __forceinline__ u64 fma2(u64 a, u64 b, u64 c) {
    u64 d;
    asm("fma.rn.f32x2 %0, %1, %2, %3;" : "=l"(d) : "l"(a), "l"(b), "l"(c));
    return d;
}
// single-instruction MUFU tanh (max abs err ~6e-4, well inside 1e-3 budget)
__device__ __forceinline__ float fast_tanh(float x) {
    float y;
    asm("tanh.approx.f32 %0, %1;" : "=f"(y) : "f"(x));
    return y;
}
// Vectorized global reduction (sm_90+)
__device__ __forceinline__ void red_add_v4(float* addr, float x, float y, float z, float w) {
    asm volatile("red.global.add.v4.f32 [%0], {%1, %2, %3, %4};"
                 :: "l"(addr), "f"(x), "f"(y), "f"(z), "f"(w) : "memory");
}

// Consume one input scalar into all 64 hidden accumulators (W1 in __constant__,
// accessed via the symbol so it stays on the LDC path).
template<int I>
__device__ __forceinline__ void consumeE1(u64* acc, float x) {
    u64 hh = pack2(x, x);
    const ulonglong2* w = (const ulonglong2*)(cEW1 + I * HID);
    #pragma unroll
    for (int q = 0; q < HID / 4; q++) {
        ulonglong2 wv = w[q];
        acc[2 * q + 0] = fma2(hh, wv.x, acc[2 * q + 0]);
        acc[2 * q + 1] = fma2(hh, wv.y, acc[2 * q + 1]);
    }
}
template<int I0>
__device__ __forceinline__ void consumeE4(u64* acc, float4 v) {
    consumeE1<I0 + 0>(acc, v.x);
    consumeE1<I0 + 1>(acc, v.y);
    consumeE1<I0 + 2>(acc, v.z);
    consumeE1<I0 + 3>(acc, v.w);
}
template<int I>
__device__ __forceinline__ void consumeN1(u64* acc, float x) {
    u64 hh = pack2(x, x);
    const ulonglong2* w = (const ulonglong2*)(cNW1 + I * HID);
    #pragma unroll
    for (int q = 0; q < HID / 4; q++) {
        ulonglong2 wv = w[q];
        acc[2 * q + 0] = fma2(hh, wv.x, acc[2 * q + 0]);
        acc[2 * q + 1] = fma2(hh, wv.y, acc[2 * q + 1]);
    }
}
template<int I0>
__device__ __forceinline__ void consumeN4(u64* acc, float4 v) {
    consumeN1<I0 + 0>(acc, v.x);
    consumeN1<I0 + 1>(acc, v.y);
    consumeN1<I0 + 2>(acc, v.z);
    consumeN1<I0 + 3>(acc, v.w);
}

// ---------------- setup kernels ----------------
__global__ void zero_kernel() {
    int i = blockIdx.x * blockDim.x + threadIdx.x;
    const int n4 = NB * NN * CHV / 4;
    if (i < n4) {
        ((float4*)g_agg_a)[i] = make_float4(0.f, 0.f, 0.f, 0.f);
        ((float4*)g_agg_b)[i] = make_float4(0.f, 0.f, 0.f, 0.f);
    }
    if (i < NN) { g_cnt_a[i] = 0; g_cnt_b[i] = 0; }
}

__global__ void count_kernel(const int* __restrict__ ca, const int* __restrict__ cb) {
    int e = blockIdx.x * blockDim.x + threadIdx.x;
    if (e < NE) {
        atomicAdd(&g_cnt_a[ca[e]], 1);
        atomicAdd(&g_cnt_b[cb[e]], 1);
    }
}

__global__ void inv_kernel() {
    int n = blockIdx.x * blockDim.x + threadIdx.x;
    if (n < NN) {
        g_inv_a[n] = 1.0f / fmaxf((float)g_cnt_a[n], 1.0f);
        g_inv_b[n] = 1.0f / fmaxf((float)g_cnt_b[n], 1.0f);
    }
}

// ---------------- edge message kernel ----------------
// One thread per (batch, edge). Streaming inputs into 32 packed accumulators;
// W1 via constant port (symbol access), W2 full via SMEM (R13-proven split).
__global__ __launch_bounds__(128, 4) void edge_kernel(
    const float* __restrict__ nv, const float* __restrict__ ev,
    const int* __restrict__ ca, const int* __restrict__ cb,
    const float* __restrict__ W2,
    float* __restrict__ out_edge)
{
    __shared__ __align__(16) float sW2[HID * CHM];   // (64,48) row-major, 12 KB
    for (int i = threadIdx.x; i < HID * CHM; i += 128) sW2[i] = W2[i];
    __syncthreads();

    int t = blockIdx.x * 128 + threadIdx.x;   // exactly NB*NE threads
    int b = t >> 18;                          // t / NE
    int e = t & (NE - 1);

    int na = ca[e];
    int nb = cb[e];

    const float4* pa = (const float4*)(nv + ((b << 15) + na) * CHV);
    const float4* pb = (const float4*)(nv + ((b << 15) + nb) * CHV);
    const float4* pe = (const float4*)(ev + (size_t)t * CHE);

    // Layer 1: 32 packed accumulators (64 hidden), inputs consumed on the fly
    u64 acc[HID / 2];
    {
        const u64* b1p = (const u64*)cEb1;
        #pragma unroll
        for (int p = 0; p < HID / 2; p++) acc[p] = b1p[p];
    }
    consumeE4< 0>(acc, pa[0]);
    consumeE4< 4>(acc, pa[1]);
    consumeE4< 8>(acc, pa[2]);
    consumeE4<12>(acc, pa[3]);
    consumeE4<16>(acc, pb[0]);
    consumeE4<20>(acc, pb[1]);
    consumeE4<24>(acc, pb[2]);
    consumeE4<28>(acc, pb[3]);
    consumeE4<32>(acc, pe[0]);
    consumeE4<36>(acc, pe[1]);
    consumeE4<40>(acc, pe[2]);
    consumeE4<44>(acc, pe[3]);

    // Layer 2 (tanh fused): weights from SMEM
    u64 m[CHM / 2];
    {
        const u64* b2p = (const u64*)cEb2;
        #pragma unroll
        for (int p = 0; p < CHM / 2; p++) m[p] = b2p[p];
    }
    #pragma unroll
    for (int p = 0; p < HID / 2; p++) {
        float lo, hi;
        unpack2(acc[p], lo, hi);
        float tl = fast_tanh(lo);
        float th = fast_tanh(hi);
        u64 t0 = pack2(tl, tl);
        u64 t1 = pack2(th, th);
        const ulonglong2* w0 = (const ulonglong2*)(sW2 + (2 * p)     * CHM);
        const ulonglong2* w1 = (const ulonglong2*)(sW2 + (2 * p + 1) * CHM);
        #pragma unroll
        for (int q = 0; q < CHM / 4; q++) {
            ulonglong2 wv0 = w0[q];
            m[2 * q + 0] = fma2(t0, wv0.x, m[2 * q + 0]);
            m[2 * q + 1] = fma2(t0, wv0.y, m[2 * q + 1]);
            ulonglong2 wv1 = w1[q];
            m[2 * q + 0] = fma2(t1, wv1.x, m[2 * q + 0]);
            m[2 * q + 1] = fma2(t1, wv1.y, m[2 * q + 1]);
        }
    }

    float mv[CHM];
    #pragma unroll
    for (int p = 0; p < CHM / 2; p++) unpack2(m[p], mv[2 * p], mv[2 * p + 1]);

    // Scatter m_a, m_b with 16B global reductions
    float* aga = g_agg_a + ((b << 15) + na) * CHV;
    red_add_v4(aga + 0,  mv[0],  mv[1],  mv[2],  mv[3]);
    red_add_v4(aga + 4,  mv[4],  mv[5],  mv[6],  mv[7]);
    red_add_v4(aga + 8,  mv[8],  mv[9],  mv[10], mv[11]);
    red_add_v4(aga + 12, mv[12], mv[13], mv[14], mv[15]);

    float* agb = g_agg_b + ((b << 15) + nb) * CHV;
    red_add_v4(agb + 0,  mv[16], mv[17], mv[18], mv[19]);
    red_add_v4(agb + 4,  mv[20], mv[21], mv[22], mv[23]);
    red_add_v4(agb + 8,  mv[24], mv[25], mv[26], mv[27]);
    red_add_v4(agb + 12, mv[28], mv[29], mv[30], mv[31]);

    // new_edge_vals = edge_vals + m_ab (re-read ev; L1 hit)
    {
        float4* oe = (float4*)(out_edge + (size_t)t * CHE);
        #pragma unroll
        for (int q = 0; q < 4; q++) {
            float4 evv = pe[q];
            oe[q] = make_float4(evv.x + mv[32 + 4 * q],
                                evv.y + mv[33 + 4 * q],
                                evv.z + mv[34 + 4 * q],
                                evv.w + mv[35 + 4 * q]);
        }
    }
}

// ---------------- node update kernel ----------------
// NW1 const (symbol access), NW2 SMEM. Straight-line streaming.
__global__ __launch_bounds__(128, 4) void node_kernel(
    const float* __restrict__ nv,
    const float* __restrict__ W2,
    float* __restrict__ out_node)
{
    __shared__ __align__(16) float sW2[HID * CHV];   // (64,16) 4 KB
    for (int i = threadIdx.x; i < HID * CHV; i += 128) sW2[i] = W2[i];
    __syncthreads();

    int t = blockIdx.x * 128 + threadIdx.x;   // exactly NB*NN threads
    int n = t & (NN - 1);

    float inva = g_inv_a[n];
    float invb = g_inv_b[n];

    const float4* pa = (const float4*)(g_agg_a + t * CHV);
    const float4* pb = (const float4*)(g_agg_b + t * CHV);
    const float4* pn = (const float4*)(nv + t * CHV);

    u64 acc[HID / 2];
    {
        const u64* b1p = (const u64*)cNb1;
        #pragma unroll
        for (int p = 0; p < HID / 2; p++) acc[p] = b1p[p];
    }
    {
        float4 v;
        v = pa[0]; v.x *= inva; v.y *= inva; v.z *= inva; v.w *= inva; consumeN4< 0>(acc, v);
        v = pa[1]; v.x *= inva; v.y *= inva; v.z *= inva; v.w *= inva; consumeN4< 4>(acc, v);
        v = pa[2]; v.x *= inva; v.y *= inva; v.z *= inva; v.w *= inva; consumeN4< 8>(acc, v);
        v = pa[3]; v.x *= inva; v.y *= inva; v.z *= inva; v.w *= inva; consumeN4<12>(acc, v);
        v = pb[0]; v.x *= invb; v.y *= invb; v.z *= invb; v.w *= invb; consumeN4<16>(acc, v);
        v = pb[1]; v.x *= invb; v.y *= invb; v.z *= invb; v.w *= invb; consumeN4<20>(acc, v);
        v = pb[2]; v.x *= invb; v.y *= invb; v.z *= invb; v.w *= invb; consumeN4<24>(acc, v);
        v = pb[3]; v.x *= invb; v.y *= invb; v.z *= invb; v.w *= invb; consumeN4<28>(acc, v);
    }
    consumeN4<32>(acc, pn[0]);
    consumeN4<36>(acc, pn[1]);
    consumeN4<40>(acc, pn[2]);
    consumeN4<44>(acc, pn[3]);

    u64 m[CHV / 2];
    {
        const u64* b2p = (const u64*)cNb2;
        #pragma unroll
        for (int p = 0; p < CHV / 2; p++) m[p] = b2p[p];
    }
    #pragma unroll
    for (int p = 0; p < HID / 2; p++) {
        float lo, hi;
        unpack2(acc[p], lo, hi);
        float tl = fast_tanh(lo);
        float th = fast_tanh(hi);
        u64 t0 = pack2(tl, tl);
        u64 t1 = pack2(th, th);
        const ulonglong2* w0 = (const ulonglong2*)(sW2 + (2 * p)     * CHV);
        const ulonglong2* w1 = (const ulonglong2*)(sW2 + (2 * p + 1) * CHV);
        #pragma unroll
        for (int q = 0; q < CHV / 4; q++) {
            ulonglong2 wv0 = w0[q];
            m[2 * q + 0] = fma2(t0, wv0.x, m[2 * q + 0]);
            m[2 * q + 1] = fma2(t0, wv0.y, m[2 * q + 1]);
            ulonglong2 wv1 = w1[q];
            m[2 * q + 0] = fma2(t1, wv1.x, m[2 * q + 0]);
            m[2 * q + 1] = fma2(t1, wv1.y, m[2 * q + 1]);
        }
    }

    float upd[CHV];
    #pragma unroll
    for (int p = 0; p < CHV / 2; p++) unpack2(m[p], upd[2 * p], upd[2 * p + 1]);

    {
        float4* on = (float4*)(out_node + t * CHV);
        #pragma unroll
        for (int q = 0; q < 4; q++) {
            float4 v = pn[q];
            on[q] = make_float4(v.x + upd[4 * q + 0], v.y + upd[4 * q + 1],
                                v.z + upd[4 * q + 2], v.w + upd[4 * q + 3]);
        }
    }
}

// ---------------- launch ----------------
extern "C" void kernel_launch(void* const* d_in, const int* in_sizes, int n_in,
                              void* d_out, int out_size) {
    const float* nv  = (const float*)d_in[0];
    const float* ev  = (const float*)d_in[1];
    const int*   ca  = (const int*)  d_in[2];
    const int*   cb  = (const int*)  d_in[3];
    const float* Wm1 = (const float*)d_in[4];
    const float* bm1 = (const float*)d_in[5];
    const float* Wm2 = (const float*)d_in[6];
    const float* bm2 = (const float*)d_in[7];
    const float* Wu1 = (const float*)d_in[8];
    const float* bu1 = (const float*)d_in[9];
    const float* Wu2 = (const float*)d_in[10];
    const float* bu2 = (const float*)d_in[11];

    float* out      = (float*)d_out;
    float* out_node = out;                       // (B, NN, CHV) first
    float* out_edge = out + NB * NN * CHV;       // (B, NE, CHE) second

    // Stage layer-1 weights + biases into constant memory (D2D, capturable)
    cudaMemcpyToSymbolAsync(cEW1, Wm1, CHM * HID * sizeof(float), 0, cudaMemcpyDeviceToDevice, 0);
    cudaMemcpyToSymbolAsync(cEb1, bm1, HID * sizeof(float),       0, cudaMemcpyDeviceToDevice, 0);
    cudaMemcpyToSymbolAsync(cEb2, bm2, CHM * sizeof(float),       0, cudaMemcpyDeviceToDevice, 0);
    cudaMemcpyToSymbolAsync(cNW1, Wu1, CHM * HID * sizeof(float), 0, cudaMemcpyDeviceToDevice, 0);
    cudaMemcpyToSymbolAsync(cNb1, bu1, HID * sizeof(float),       0, cudaMemcpyDeviceToDevice, 0);
    cudaMemcpyToSymbolAsync(cNb2, bu2, CHV * sizeof(float),       0, cudaMemcpyDeviceToDevice, 0);

    zero_kernel <<< (NB * NN * CHV / 4 + 255) / 256, 256 >>> ();
    count_kernel<<< NE / 256, 256 >>> (ca, cb);
    inv_kernel  <<< NN / 256, 256 >>> ();
    edge_kernel <<< NB * NE / 128, 128 >>> (nv, ev, ca, cb, Wm2, out_edge);
    node_kernel <<< NB * NN / 128, 128 >>> (nv, Wu2, out_node);
}